// round 10
// baseline (speedup 1.0000x reference)
#include <cuda_runtime.h>
#include <cuda_fp16.h>
#include <math.h>

#define NN 50000
#define EE 1600000
#define GG 64
#define NB 98            // (NN+511)/512 scan blocks

typedef unsigned long long u64;

// ---------------- device scratch ----------------
__device__ __align__(16) __half g_xlh[NN * 64];   // fp16 gather table
__device__ __align__(16) float g_xr[NN * 64];
__device__ __align__(16) float g_h1[NN * 64];
__device__ __align__(16) float g_gsum[GG * 64];
__device__ float g_gcnt[GG];
__device__ int   g_cnt[NN];
__device__ int   g_off[NN];
__device__ int   g_cursor[NN];
__device__ int   g_bsum[128];
__device__ __align__(16) int2 g_edges[EE];        // (src, ea-bits) interleaved

// ---------------- f32x2 helpers (FFMA2, PTX-only) ----------------
__device__ __forceinline__ u64 ffma2(u64 a, u64 b, u64 c) {
    u64 d;
    asm("fma.rn.f32x2 %0, %1, %2, %3;" : "=l"(d) : "l"(a), "l"(b), "l"(c));
    return d;
}
__device__ __forceinline__ u64 pack2(float x) {
    u64 d;
    asm("mov.b64 %0, {%1, %1};" : "=l"(d) : "f"(x));
    return d;
}
__device__ __forceinline__ void unpack2(u64 v, float& lo, float& hi) {
    asm("mov.b64 {%0, %1}, %2;" : "=f"(lo), "=f"(hi) : "l"(v));
}

// ---------------- init ----------------
__global__ void k_init0() {
    int i = blockIdx.x * blockDim.x + threadIdx.x;
    if (i < NN) g_cnt[i] = 0;
    if (i < GG * 64) g_gsum[i] = 0.f;
    if (i < GG) g_gcnt[i] = 0.f;
}

// ---------------- CSR build ----------------
__global__ void k_hist(const int* __restrict__ dst) {
    int e = blockIdx.x * blockDim.x + threadIdx.x;
    if (e >= EE) return;
    atomicAdd(&g_cnt[dst[e]], 1);
}

__global__ void k_scan1() {            // 512 threads/block, NB blocks
    __shared__ int wsum[16];
    int i = blockIdx.x * 512 + threadIdx.x;
    int lane = threadIdx.x & 31, wid = threadIdx.x >> 5;
    int v = (i < NN) ? g_cnt[i] : 0;
    int x = v;
#pragma unroll
    for (int o = 1; o < 32; o <<= 1) {
        int y = __shfl_up_sync(0xffffffffu, x, o);
        if (lane >= o) x += y;
    }
    if (lane == 31) wsum[wid] = x;
    __syncthreads();
    if (wid == 0) {
        int s = (lane < 16) ? wsum[lane] : 0;
#pragma unroll
        for (int o = 1; o < 16; o <<= 1) {
            int y = __shfl_up_sync(0xffffffffu, s, o);
            if (lane >= o) s += y;
        }
        if (lane < 16) wsum[lane] = s;
    }
    __syncthreads();
    int prefix = (wid > 0) ? wsum[wid - 1] : 0;
    if (i < NN) g_off[i] = prefix + x - v;        // exclusive within block
    if (threadIdx.x == 511) g_bsum[blockIdx.x] = prefix + x;  // block total
}

__global__ void k_scan3() {            // per-block prefix over block sums, then finalize
    __shared__ int bpref;
    int b = blockIdx.x;
    if (threadIdx.x < 32) {
        int s = 0;
        for (int j = threadIdx.x; j < b; j += 32) s += g_bsum[j];
#pragma unroll
        for (int o = 16; o; o >>= 1) s += __shfl_xor_sync(0xffffffffu, s, o);
        if (threadIdx.x == 0) bpref = s;
    }
    __syncthreads();
    int i = b * 512 + threadIdx.x;
    if (i < NN) {
        int o = g_off[i] + bpref;
        g_off[i] = o;
        g_cursor[i] = o;
    }
}

__global__ void k_escatter(const int* __restrict__ src, const int* __restrict__ dst,
                           const float* __restrict__ ea) {
    int e = blockIdx.x * blockDim.x + threadIdx.x;
    if (e >= EE) return;
    int d = dst[e];
    int pos = atomicAdd(&g_cursor[d], 1);
    g_edges[pos] = make_int2(src[e], __float_as_int(ea[e]));
}

// ---------------- fused dual GEMM: xl = X@Wl+bl (fp16 out), xr = X@Wr+br --------------
template <int K, int USE_H1>
__global__ __launch_bounds__(256) void k_gemm2(
        const float* __restrict__ Xg,
        const float* __restrict__ Wl, const float* __restrict__ bl,
        const float* __restrict__ Wr, const float* __restrict__ br) {
    extern __shared__ float sh[];
    float* Wls = sh;                 // K*64
    float* Wrs = sh + K * 64;        // K*64
    float* Xs  = sh + 2 * K * 64;    // 64*K

    int t = threadIdx.x;
    int base = blockIdx.x * 64;
    const float* __restrict__ X = USE_H1 ? g_h1 : Xg;

    for (int i = t; i < K * 16; i += 256) {
        *(float4*)&Wls[i * 4] = __ldg((const float4*)&Wl[i * 4]);
        *(float4*)&Wrs[i * 4] = __ldg((const float4*)&Wr[i * 4]);
    }
    const int K4 = K / 4;
    for (int i = t; i < 64 * K4; i += 256) {
        int row = i / K4, c4 = i - row * K4;
        int node = base + row;
        float4 v = make_float4(0.f, 0.f, 0.f, 0.f);
        if (node < NN) v = __ldg((const float4*)&X[(size_t)node * K + c4 * 4]);
        *(float4*)&Xs[row * K + c4 * 4] = v;
    }
    __syncthreads();

    int cg = t & 15;            // 4 output channels
    int ng = t >> 4;            // 4 nodes
    int nb = base + ng * 4;

    u64 bl0 = *(const u64*)&bl[cg * 4];
    u64 bl1 = *(const u64*)&bl[cg * 4 + 2];
    u64 br0 = *(const u64*)&br[cg * 4];
    u64 br1 = *(const u64*)&br[cg * 4 + 2];

    u64 accL[4][2], accR[4][2];
#pragma unroll
    for (int n = 0; n < 4; n++) {
        accL[n][0] = bl0; accL[n][1] = bl1;
        accR[n][0] = br0; accR[n][1] = br1;
    }

    const float* xs0 = &Xs[(ng * 4 + 0) * K];
    const float* xs1 = &Xs[(ng * 4 + 1) * K];
    const float* xs2 = &Xs[(ng * 4 + 2) * K];
    const float* xs3 = &Xs[(ng * 4 + 3) * K];

#pragma unroll 4
    for (int k = 0; k < K; k++) {
        ulonglong2 wl = *(const ulonglong2*)&Wls[k * 64 + cg * 4];
        ulonglong2 wr = *(const ulonglong2*)&Wrs[k * 64 + cg * 4];
        u64 x0 = pack2(xs0[k]);
        u64 x1 = pack2(xs1[k]);
        u64 x2 = pack2(xs2[k]);
        u64 x3 = pack2(xs3[k]);
        accL[0][0] = ffma2(x0, wl.x, accL[0][0]);  accL[0][1] = ffma2(x0, wl.y, accL[0][1]);
        accR[0][0] = ffma2(x0, wr.x, accR[0][0]);  accR[0][1] = ffma2(x0, wr.y, accR[0][1]);
        accL[1][0] = ffma2(x1, wl.x, accL[1][0]);  accL[1][1] = ffma2(x1, wl.y, accL[1][1]);
        accR[1][0] = ffma2(x1, wr.x, accR[1][0]);  accR[1][1] = ffma2(x1, wr.y, accR[1][1]);
        accL[2][0] = ffma2(x2, wl.x, accL[2][0]);  accL[2][1] = ffma2(x2, wl.y, accL[2][1]);
        accR[2][0] = ffma2(x2, wr.x, accR[2][0]);  accR[2][1] = ffma2(x2, wr.y, accR[2][1]);
        accL[3][0] = ffma2(x3, wl.x, accL[3][0]);  accL[3][1] = ffma2(x3, wl.y, accL[3][1]);
        accR[3][0] = ffma2(x3, wr.x, accR[3][0]);  accR[3][1] = ffma2(x3, wr.y, accR[3][1]);
    }

#pragma unroll
    for (int n = 0; n < 4; n++) {
        if (nb + n < NN) {
            float4 L, R;
            unpack2(accL[n][0], L.x, L.y);  unpack2(accL[n][1], L.z, L.w);
            unpack2(accR[n][0], R.x, R.y);  unpack2(accR[n][1], R.z, R.w);
            __half2 h01 = __floats2half2_rn(L.x, L.y);
            __half2 h23 = __floats2half2_rn(L.z, L.w);
            uint2 hv;
            hv.x = *(unsigned*)&h01;
            hv.y = *(unsigned*)&h23;
            *(uint2*)&g_xlh[(size_t)(nb + n) * 64 + cg * 4] = hv;
            *(float4*)&g_xr[(size_t)(nb + n) * 64 + cg * 4] = R;
        }
    }
}

// ---------------- warp-per-dst edge pass: 8 threads/edge, 4 edges in flight, pipelined ---
template <int LAYER>
__global__ __launch_bounds__(256) void k_edge_sorted(
        const float* __restrict__ We, const float* __restrict__ att,
        const float* __restrict__ bias, const int* __restrict__ batch) {
    int gw = (blockIdx.x * 256 + threadIdx.x) >> 5;
    if (gw >= NN) return;
    int lane = threadIdx.x & 31;
    int q  = lane >> 3;          // quarter 0..3 (edge slot)
    int cg = lane & 7;           // 8 channels: [cg*8, cg*8+8)
    unsigned m8 = 0xFFu << (q * 8);

    int d = gw;
    int off = g_off[d], cnt = g_cnt[d];
    int end = off + cnt;

    const float* xrp = &g_xr[(size_t)d * 64 + cg * 8];
    float4 b0 = *(const float4*)xrp;
    float4 b1 = *(const float4*)(xrp + 4);
    float4 w0 = __ldg((const float4*)&We[cg * 8]);
    float4 w1 = __ldg((const float4*)&We[cg * 8 + 4]);
    float4 at0 = __ldg((const float4*)&att[cg * 8]);
    float4 at1 = __ldg((const float4*)&att[cg * 8 + 4]);

    float4 acc0 = make_float4(0.f, 0.f, 0.f, 0.f);
    float4 acc1 = make_float4(0.f, 0.f, 0.f, 0.f);
    float den = 0.f, easum = 0.f;

    // software pipeline: prefetch next iteration's edge + gather
    int i = off + q;
    int2 ed = make_int2(0, 0);
    uint4 u = make_uint4(0, 0, 0, 0);
    if (i < end) {
        ed = g_edges[i];
        u = *(const uint4*)&g_xlh[(size_t)ed.x * 64 + cg * 8];
    }
    while (i < end) {
        int inext = i + 4;
        int2 edn = make_int2(0, 0);
        uint4 un = make_uint4(0, 0, 0, 0);
        if (inext < end) {
            edn = g_edges[inext];
            un = *(const uint4*)&g_xlh[(size_t)edn.x * 64 + cg * 8];
        }
        float ea = __int_as_float(ed.y);
        easum += ea;
        float2 f0 = __half22float2(*(__half2*)&u.x);
        float2 f1 = __half22float2(*(__half2*)&u.y);
        float2 f2 = __half22float2(*(__half2*)&u.z);
        float2 f3 = __half22float2(*(__half2*)&u.w);
        float v0 = f0.x + b0.x + ea * w0.x;  v0 = v0 > 0.f ? v0 : 0.2f * v0;
        float v1 = f0.y + b0.y + ea * w0.y;  v1 = v1 > 0.f ? v1 : 0.2f * v1;
        float v2 = f1.x + b0.z + ea * w0.z;  v2 = v2 > 0.f ? v2 : 0.2f * v2;
        float v3 = f1.y + b0.w + ea * w0.w;  v3 = v3 > 0.f ? v3 : 0.2f * v3;
        float v4 = f2.x + b1.x + ea * w1.x;  v4 = v4 > 0.f ? v4 : 0.2f * v4;
        float v5 = f2.y + b1.y + ea * w1.y;  v5 = v5 > 0.f ? v5 : 0.2f * v5;
        float v6 = f3.x + b1.z + ea * w1.z;  v6 = v6 > 0.f ? v6 : 0.2f * v6;
        float v7 = f3.y + b1.w + ea * w1.w;  v7 = v7 > 0.f ? v7 : 0.2f * v7;
        float lg = v0 * at0.x + v1 * at0.y + v2 * at0.z + v3 * at0.w
                 + v4 * at1.x + v5 * at1.y + v6 * at1.z + v7 * at1.w;
        lg += __shfl_xor_sync(m8, lg, 4);
        lg += __shfl_xor_sync(m8, lg, 2);
        lg += __shfl_xor_sync(m8, lg, 1);
        float p = __expf(lg);
        den += p;
        acc0.x += p * f0.x; acc0.y += p * f0.y; acc0.z += p * f1.x; acc0.w += p * f1.y;
        acc1.x += p * f2.x; acc1.y += p * f2.y; acc1.z += p * f3.x; acc1.w += p * f3.y;
        i = inext; ed = edn; u = un;
    }
    __syncwarp();
    // combine the 4 quarters (each holds partials for the same channel slice cg)
#pragma unroll
    for (int o = 8; o <= 16; o <<= 1) {
        acc0.x += __shfl_xor_sync(0xffffffffu, acc0.x, o);
        acc0.y += __shfl_xor_sync(0xffffffffu, acc0.y, o);
        acc0.z += __shfl_xor_sync(0xffffffffu, acc0.z, o);
        acc0.w += __shfl_xor_sync(0xffffffffu, acc0.w, o);
        acc1.x += __shfl_xor_sync(0xffffffffu, acc1.x, o);
        acc1.y += __shfl_xor_sync(0xffffffffu, acc1.y, o);
        acc1.z += __shfl_xor_sync(0xffffffffu, acc1.z, o);
        acc1.w += __shfl_xor_sync(0xffffffffu, acc1.w, o);
        den   += __shfl_xor_sync(0xffffffffu, den, o);
        easum += __shfl_xor_sync(0xffffffffu, easum, o);
    }

    // self-loop edge: src = dst, ea = mean of incoming edge attrs (all quarters redundant)
    {
        float lea = easum / fmaxf((float)cnt, 1.f);
        uint4 ud = *(const uint4*)&g_xlh[(size_t)d * 64 + cg * 8];
        float2 f0 = __half22float2(*(__half2*)&ud.x);
        float2 f1 = __half22float2(*(__half2*)&ud.y);
        float2 f2 = __half22float2(*(__half2*)&ud.z);
        float2 f3 = __half22float2(*(__half2*)&ud.w);
        float v0 = f0.x + b0.x + lea * w0.x;  v0 = v0 > 0.f ? v0 : 0.2f * v0;
        float v1 = f0.y + b0.y + lea * w0.y;  v1 = v1 > 0.f ? v1 : 0.2f * v1;
        float v2 = f1.x + b0.z + lea * w0.z;  v2 = v2 > 0.f ? v2 : 0.2f * v2;
        float v3 = f1.y + b0.w + lea * w0.w;  v3 = v3 > 0.f ? v3 : 0.2f * v3;
        float v4 = f2.x + b1.x + lea * w1.x;  v4 = v4 > 0.f ? v4 : 0.2f * v4;
        float v5 = f2.y + b1.y + lea * w1.y;  v5 = v5 > 0.f ? v5 : 0.2f * v5;
        float v6 = f3.x + b1.z + lea * w1.z;  v6 = v6 > 0.f ? v6 : 0.2f * v6;
        float v7 = f3.y + b1.w + lea * w1.w;  v7 = v7 > 0.f ? v7 : 0.2f * v7;
        float lg = v0 * at0.x + v1 * at0.y + v2 * at0.z + v3 * at0.w
                 + v4 * at1.x + v5 * at1.y + v6 * at1.z + v7 * at1.w;
        lg += __shfl_xor_sync(0xffffffffu, lg, 4);
        lg += __shfl_xor_sync(0xffffffffu, lg, 2);
        lg += __shfl_xor_sync(0xffffffffu, lg, 1);
        float p = __expf(lg);
        den += p;
        acc0.x += p * f0.x; acc0.y += p * f0.y; acc0.z += p * f1.x; acc0.w += p * f1.y;
        acc1.x += p * f2.x; acc1.y += p * f2.y; acc1.z += p * f3.x; acc1.w += p * f3.y;
    }

    float inv = 1.f / (den + 1e-16f);
    float4 bias0 = __ldg((const float4*)&bias[cg * 8]);
    float4 bias1 = __ldg((const float4*)&bias[cg * 8 + 4]);
    float h0 = acc0.x * inv + bias0.x;  h0 = h0 > 0.f ? h0 : expm1f(h0);
    float h1 = acc0.y * inv + bias0.y;  h1 = h1 > 0.f ? h1 : expm1f(h1);
    float h2 = acc0.z * inv + bias0.z;  h2 = h2 > 0.f ? h2 : expm1f(h2);
    float h3 = acc0.w * inv + bias0.w;  h3 = h3 > 0.f ? h3 : expm1f(h3);
    float h4 = acc1.x * inv + bias1.x;  h4 = h4 > 0.f ? h4 : expm1f(h4);
    float h5 = acc1.y * inv + bias1.y;  h5 = h5 > 0.f ? h5 : expm1f(h5);
    float h6 = acc1.z * inv + bias1.z;  h6 = h6 > 0.f ? h6 : expm1f(h6);
    float h7 = acc1.w * inv + bias1.w;  h7 = h7 > 0.f ? h7 : expm1f(h7);

    if (q == 0) {
        if (LAYER == 0) {
            float* hp = &g_h1[(size_t)d * 64 + cg * 8];
            *(float4*)hp       = make_float4(h0, h1, h2, h3);
            *(float4*)(hp + 4) = make_float4(h4, h5, h6, h7);
        } else {
            int g = batch[d];
            float* ptr = &g_gsum[g * 64 + cg * 8];
            asm volatile("red.global.add.v4.f32 [%0], {%1, %2, %3, %4};"
                         :: "l"(ptr), "f"(h0), "f"(h1), "f"(h2), "f"(h3)
                         : "memory");
            asm volatile("red.global.add.v4.f32 [%0], {%1, %2, %3, %4};"
                         :: "l"(ptr + 4), "f"(h4), "f"(h5), "f"(h6), "f"(h7)
                         : "memory");
            if (cg == 0) atomicAdd(&g_gcnt[g], 1.f);
        }
    }
}

// ---------------- head: relu(fc1) -> BN(eval) -> fc3 ----------------
__global__ void k_head(const float* __restrict__ Wfc1, const float* __restrict__ bfc1,
                       const float* __restrict__ gamma, const float* __restrict__ beta,
                       const float* __restrict__ mean, const float* __restrict__ var,
                       const float* __restrict__ Wfc3, const float* __restrict__ bfc3,
                       float* __restrict__ out) {
    int g = threadIdx.x;
    if (g >= GG) return;
    float cnt = fmaxf(g_gcnt[g], 1.f);
    float pooled[64];
#pragma unroll
    for (int c = 0; c < 64; c++) pooled[c] = g_gsum[g * 64 + c] / cnt;
    float acc = bfc3[0];
    for (int j = 0; j < 32; j++) {
        float z = bfc1[j];
#pragma unroll
        for (int c = 0; c < 64; c++) z = fmaf(pooled[c], Wfc1[c * 32 + j], z);
        z = fmaxf(z, 0.f);
        z = (z - mean[j]) * rsqrtf(var[j] + 1e-5f) * gamma[j] + beta[j];
        acc = fmaf(z, Wfc3[j], acc);
    }
    out[g] = acc;
}

// ---------------- launch ----------------
extern "C" void kernel_launch(void* const* d_in, const int* in_sizes, int n_in,
                              void* d_out, int out_size) {
    const float* x      = (const float*)d_in[0];
    const int*   eidx   = (const int*)d_in[1];
    const float* eattr  = (const float*)d_in[2];
    const int*   batch  = (const int*)d_in[3];
    const float* Wl1 = (const float*)d_in[4];   const float* bl1 = (const float*)d_in[5];
    const float* Wr1 = (const float*)d_in[6];   const float* br1 = (const float*)d_in[7];
    const float* We1 = (const float*)d_in[8];   const float* att1 = (const float*)d_in[9];
    const float* bias1 = (const float*)d_in[10];
    const float* Wl2 = (const float*)d_in[11];  const float* bl2 = (const float*)d_in[12];
    const float* Wr2 = (const float*)d_in[13];  const float* br2 = (const float*)d_in[14];
    const float* We2 = (const float*)d_in[15];  const float* att2 = (const float*)d_in[16];
    const float* bias2 = (const float*)d_in[17];
    const float* Wfc1 = (const float*)d_in[18]; const float* bfc1 = (const float*)d_in[19];
    const float* gamma = (const float*)d_in[20]; const float* beta = (const float*)d_in[21];
    const float* mean = (const float*)d_in[22];  const float* var = (const float*)d_in[23];
    const float* Wfc3 = (const float*)d_in[24];  const float* bfc3 = (const float*)d_in[25];
    float* out = (float*)d_out;

    const int* e_src = eidx;        // edge_index[0]
    const int* e_dst = eidx + EE;   // edge_index[1]

    const int TB = 256;
    const int nBlocksN    = (NN + TB - 1) / TB;
    const int nBlocksE    = (EE + TB - 1) / TB;
    const int nBlocksGemm = (NN + 63) / 64;
    const int nBlocksWarp = (NN * 32 + TB - 1) / TB;    // warp per dst

    const int smem1 = (2 * 128 * 64 + 64 * 128) * 4;    // 96 KB
    const int smem2 = (2 * 64 * 64 + 64 * 64) * 4;      // 48 KB
    cudaFuncSetAttribute(k_gemm2<128, 0>, cudaFuncAttributeMaxDynamicSharedMemorySize, smem1);
    cudaFuncSetAttribute(k_gemm2<64, 1>,  cudaFuncAttributeMaxDynamicSharedMemorySize, smem2);

    // ---- CSR build (once; reused by both layers) ----
    k_init0<<<nBlocksN, TB>>>();
    k_hist<<<nBlocksE, TB>>>(e_dst);
    k_scan1<<<NB, 512>>>();
    k_scan3<<<NB, 512>>>();
    k_escatter<<<nBlocksE, TB>>>(e_src, e_dst, eattr);

    // ---- layer 1 ----
    k_gemm2<128, 0><<<nBlocksGemm, TB, smem1>>>(x, Wl1, bl1, Wr1, br1);
    k_edge_sorted<0><<<nBlocksWarp, TB>>>(We1, att1, bias1, nullptr);   // -> g_h1

    // ---- layer 2 ----
    k_gemm2<64, 1><<<nBlocksGemm, TB, smem2>>>(nullptr, Wl2, bl2, Wr2, br2);
    k_edge_sorted<1><<<nBlocksWarp, TB>>>(We2, att2, bias2, batch);     // -> pool

    // ---- head ----
    k_head<<<1, 64>>>(Wfc1, bfc1, gamma, beta, mean, var, Wfc3, bfc3, out);
}

// round 11
// speedup vs baseline: 1.0933x; 1.0933x over previous
#include <cuda_runtime.h>
#include <cuda_fp16.h>
#include <math.h>

#define NN 50000
#define EE 1600000
#define GG 64
#define NB 98            // (NN+511)/512 scan blocks

typedef unsigned long long u64;

// ---------------- device scratch ----------------
__device__ __align__(16) __half g_xlh[NN * 64];   // fp16 gather table
__device__ __align__(16) float g_xr[NN * 64];
__device__ __align__(16) float g_h1[NN * 64];
__device__ __align__(16) float g_gsum[GG * 64];
__device__ float g_gcnt[GG];
__device__ int   g_cnt[NN];
__device__ int   g_off[NN];
__device__ int   g_cursor[NN];
__device__ int   g_bsum[128];
__device__ __align__(16) int2 g_edges[EE];        // (src, ea-bits) interleaved

// ---------------- f32x2 helpers (FFMA2, PTX-only) ----------------
__device__ __forceinline__ u64 ffma2(u64 a, u64 b, u64 c) {
    u64 d;
    asm("fma.rn.f32x2 %0, %1, %2, %3;" : "=l"(d) : "l"(a), "l"(b), "l"(c));
    return d;
}
__device__ __forceinline__ u64 pack2(float x) {
    u64 d;
    asm("mov.b64 %0, {%1, %1};" : "=l"(d) : "f"(x));
    return d;
}
__device__ __forceinline__ void unpack2(u64 v, float& lo, float& hi) {
    asm("mov.b64 {%0, %1}, %2;" : "=f"(lo), "=f"(hi) : "l"(v));
}

// ---------------- init ----------------
__global__ void k_init0() {
    int i = blockIdx.x * blockDim.x + threadIdx.x;
    if (i < NN) g_cnt[i] = 0;
    if (i < GG * 64) g_gsum[i] = 0.f;
    if (i < GG) g_gcnt[i] = 0.f;
}

// ---------------- CSR build ----------------
__global__ void k_hist(const int* __restrict__ dst) {
    int e = blockIdx.x * blockDim.x + threadIdx.x;
    if (e >= EE) return;
    atomicAdd(&g_cnt[dst[e]], 1);
}

__global__ void k_scan1() {            // 512 threads/block, NB blocks
    __shared__ int wsum[16];
    int i = blockIdx.x * 512 + threadIdx.x;
    int lane = threadIdx.x & 31, wid = threadIdx.x >> 5;
    int v = (i < NN) ? g_cnt[i] : 0;
    int x = v;
#pragma unroll
    for (int o = 1; o < 32; o <<= 1) {
        int y = __shfl_up_sync(0xffffffffu, x, o);
        if (lane >= o) x += y;
    }
    if (lane == 31) wsum[wid] = x;
    __syncthreads();
    if (wid == 0) {
        int s = (lane < 16) ? wsum[lane] : 0;
#pragma unroll
        for (int o = 1; o < 16; o <<= 1) {
            int y = __shfl_up_sync(0xffffffffu, s, o);
            if (lane >= o) s += y;
        }
        if (lane < 16) wsum[lane] = s;
    }
    __syncthreads();
    int prefix = (wid > 0) ? wsum[wid - 1] : 0;
    if (i < NN) g_off[i] = prefix + x - v;        // exclusive within block
    if (threadIdx.x == 511) g_bsum[blockIdx.x] = prefix + x;  // block total
}

__global__ void k_scan3() {            // per-block prefix over block sums, then finalize
    __shared__ int bpref;
    int b = blockIdx.x;
    if (threadIdx.x < 32) {
        int s = 0;
        for (int j = threadIdx.x; j < b; j += 32) s += g_bsum[j];
#pragma unroll
        for (int o = 16; o; o >>= 1) s += __shfl_xor_sync(0xffffffffu, s, o);
        if (threadIdx.x == 0) bpref = s;
    }
    __syncthreads();
    int i = b * 512 + threadIdx.x;
    if (i < NN) {
        int o = g_off[i] + bpref;
        g_off[i] = o;
        g_cursor[i] = o;
    }
}

__global__ void k_escatter(const int* __restrict__ src, const int* __restrict__ dst,
                           const float* __restrict__ ea) {
    int e = blockIdx.x * blockDim.x + threadIdx.x;
    if (e >= EE) return;
    int d = dst[e];
    int pos = atomicAdd(&g_cursor[d], 1);
    g_edges[pos] = make_int2(src[e], __float_as_int(ea[e]));
}

// ---------------- fused dual GEMM: xl = X@Wl+bl (fp16 out), xr = X@Wr+br --------------
template <int K, int USE_H1>
__global__ __launch_bounds__(256) void k_gemm2(
        const float* __restrict__ Xg,
        const float* __restrict__ Wl, const float* __restrict__ bl,
        const float* __restrict__ Wr, const float* __restrict__ br) {
    extern __shared__ float sh[];
    float* Wls = sh;                 // K*64
    float* Wrs = sh + K * 64;        // K*64
    float* Xs  = sh + 2 * K * 64;    // 64*K

    int t = threadIdx.x;
    int base = blockIdx.x * 64;
    const float* __restrict__ X = USE_H1 ? g_h1 : Xg;

    for (int i = t; i < K * 16; i += 256) {
        *(float4*)&Wls[i * 4] = __ldg((const float4*)&Wl[i * 4]);
        *(float4*)&Wrs[i * 4] = __ldg((const float4*)&Wr[i * 4]);
    }
    const int K4 = K / 4;
    for (int i = t; i < 64 * K4; i += 256) {
        int row = i / K4, c4 = i - row * K4;
        int node = base + row;
        float4 v = make_float4(0.f, 0.f, 0.f, 0.f);
        if (node < NN) v = __ldg((const float4*)&X[(size_t)node * K + c4 * 4]);
        *(float4*)&Xs[row * K + c4 * 4] = v;
    }
    __syncthreads();

    int cg = t & 15;            // 4 output channels
    int ng = t >> 4;            // 4 nodes
    int nb = base + ng * 4;

    u64 bl0 = *(const u64*)&bl[cg * 4];
    u64 bl1 = *(const u64*)&bl[cg * 4 + 2];
    u64 br0 = *(const u64*)&br[cg * 4];
    u64 br1 = *(const u64*)&br[cg * 4 + 2];

    u64 accL[4][2], accR[4][2];
#pragma unroll
    for (int n = 0; n < 4; n++) {
        accL[n][0] = bl0; accL[n][1] = bl1;
        accR[n][0] = br0; accR[n][1] = br1;
    }

    const float* xs0 = &Xs[(ng * 4 + 0) * K];
    const float* xs1 = &Xs[(ng * 4 + 1) * K];
    const float* xs2 = &Xs[(ng * 4 + 2) * K];
    const float* xs3 = &Xs[(ng * 4 + 3) * K];

#pragma unroll 4
    for (int k = 0; k < K; k++) {
        ulonglong2 wl = *(const ulonglong2*)&Wls[k * 64 + cg * 4];
        ulonglong2 wr = *(const ulonglong2*)&Wrs[k * 64 + cg * 4];
        u64 x0 = pack2(xs0[k]);
        u64 x1 = pack2(xs1[k]);
        u64 x2 = pack2(xs2[k]);
        u64 x3 = pack2(xs3[k]);
        accL[0][0] = ffma2(x0, wl.x, accL[0][0]);  accL[0][1] = ffma2(x0, wl.y, accL[0][1]);
        accR[0][0] = ffma2(x0, wr.x, accR[0][0]);  accR[0][1] = ffma2(x0, wr.y, accR[0][1]);
        accL[1][0] = ffma2(x1, wl.x, accL[1][0]);  accL[1][1] = ffma2(x1, wl.y, accL[1][1]);
        accR[1][0] = ffma2(x1, wr.x, accR[1][0]);  accR[1][1] = ffma2(x1, wr.y, accR[1][1]);
        accL[2][0] = ffma2(x2, wl.x, accL[2][0]);  accL[2][1] = ffma2(x2, wl.y, accL[2][1]);
        accR[2][0] = ffma2(x2, wr.x, accR[2][0]);  accR[2][1] = ffma2(x2, wr.y, accR[2][1]);
        accL[3][0] = ffma2(x3, wl.x, accL[3][0]);  accL[3][1] = ffma2(x3, wl.y, accL[3][1]);
        accR[3][0] = ffma2(x3, wr.x, accR[3][0]);  accR[3][1] = ffma2(x3, wr.y, accR[3][1]);
    }

#pragma unroll
    for (int n = 0; n < 4; n++) {
        if (nb + n < NN) {
            float4 L, R;
            unpack2(accL[n][0], L.x, L.y);  unpack2(accL[n][1], L.z, L.w);
            unpack2(accR[n][0], R.x, R.y);  unpack2(accR[n][1], R.z, R.w);
            __half2 h01 = __floats2half2_rn(L.x, L.y);
            __half2 h23 = __floats2half2_rn(L.z, L.w);
            uint2 hv;
            hv.x = *(unsigned*)&h01;
            hv.y = *(unsigned*)&h23;
            *(uint2*)&g_xlh[(size_t)(nb + n) * 64 + cg * 4] = hv;
            *(float4*)&g_xr[(size_t)(nb + n) * 64 + cg * 4] = R;
        }
    }
}

// ---------------- warp-per-dst edge pass over CSR (fp16 xl gathers) ----------------
// 16 threads/edge, 2 half-slots/warp, 2 edges unrolled per slot (4 edges in flight).
template <int LAYER>
__global__ __launch_bounds__(256) void k_edge_sorted(
        const float* __restrict__ We, const float* __restrict__ att,
        const float* __restrict__ bias, const int* __restrict__ batch) {
    int gw = (blockIdx.x * 256 + threadIdx.x) >> 5;
    if (gw >= NN) return;
    int lane = threadIdx.x & 31;
    int half = lane >> 4, cg = lane & 15;
    unsigned m16 = 0xFFFFu << (half * 16);

    int d = gw;
    int off = g_off[d], cnt = g_cnt[d];
    int end = off + cnt;

    float4 b  = *(const float4*)&g_xr[(size_t)d * 64 + cg * 4];
    float4 w4 = __ldg((const float4*)&We[cg * 4]);
    float4 at = __ldg((const float4*)&att[cg * 4]);

    float4 acc = make_float4(0.f, 0.f, 0.f, 0.f);
    float den = 0.f, easum = 0.f;

    int i = off + half;
    // main loop: 2 edges per slot, loads batched, shfl chains interleaved
    for (; i + 2 < end; i += 4) {
        int2 e0 = g_edges[i];
        int2 e1 = g_edges[i + 2];
        uint2 u0 = *(const uint2*)&g_xlh[(size_t)e0.x * 64 + cg * 4];
        uint2 u1 = *(const uint2*)&g_xlh[(size_t)e1.x * 64 + cg * 4];
        float ea0 = __int_as_float(e0.y);
        float ea1 = __int_as_float(e1.y);
        easum += ea0 + ea1;
        float2 a01 = __half22float2(*(__half2*)&u0.x);
        float2 a23 = __half22float2(*(__half2*)&u0.y);
        float2 c01 = __half22float2(*(__half2*)&u1.x);
        float2 c23 = __half22float2(*(__half2*)&u1.y);

        float p0x = a01.x + b.x + ea0 * w4.x;  p0x = p0x > 0.f ? p0x : 0.2f * p0x;
        float p0y = a01.y + b.y + ea0 * w4.y;  p0y = p0y > 0.f ? p0y : 0.2f * p0y;
        float p0z = a23.x + b.z + ea0 * w4.z;  p0z = p0z > 0.f ? p0z : 0.2f * p0z;
        float p0w = a23.y + b.w + ea0 * w4.w;  p0w = p0w > 0.f ? p0w : 0.2f * p0w;
        float q0x = c01.x + b.x + ea1 * w4.x;  q0x = q0x > 0.f ? q0x : 0.2f * q0x;
        float q0y = c01.y + b.y + ea1 * w4.y;  q0y = q0y > 0.f ? q0y : 0.2f * q0y;
        float q0z = c23.x + b.z + ea1 * w4.z;  q0z = q0z > 0.f ? q0z : 0.2f * q0z;
        float q0w = c23.y + b.w + ea1 * w4.w;  q0w = q0w > 0.f ? q0w : 0.2f * q0w;

        float lg0 = p0x * at.x + p0y * at.y + p0z * at.z + p0w * at.w;
        float lg1 = q0x * at.x + q0y * at.y + q0z * at.z + q0w * at.w;
        lg0 += __shfl_xor_sync(m16, lg0, 8);
        lg1 += __shfl_xor_sync(m16, lg1, 8);
        lg0 += __shfl_xor_sync(m16, lg0, 4);
        lg1 += __shfl_xor_sync(m16, lg1, 4);
        lg0 += __shfl_xor_sync(m16, lg0, 2);
        lg1 += __shfl_xor_sync(m16, lg1, 2);
        lg0 += __shfl_xor_sync(m16, lg0, 1);
        lg1 += __shfl_xor_sync(m16, lg1, 1);

        float pe0 = __expf(lg0);
        float pe1 = __expf(lg1);
        den += pe0 + pe1;
        acc.x += pe0 * a01.x + pe1 * c01.x;
        acc.y += pe0 * a01.y + pe1 * c01.y;
        acc.z += pe0 * a23.x + pe1 * c23.x;
        acc.w += pe0 * a23.y + pe1 * c23.y;
    }
    // remainder (<=1 edge per slot)
    for (; i < end; i += 2) {
        int2 ed = g_edges[i];
        float ea = __int_as_float(ed.y);
        easum += ea;
        uint2 u = *(const uint2*)&g_xlh[(size_t)ed.x * 64 + cg * 4];
        float2 f01 = __half22float2(*(__half2*)&u.x);
        float2 f23 = __half22float2(*(__half2*)&u.y);
        float vx = f01.x + b.x + ea * w4.x;  vx = vx > 0.f ? vx : 0.2f * vx;
        float vy = f01.y + b.y + ea * w4.y;  vy = vy > 0.f ? vy : 0.2f * vy;
        float vz = f23.x + b.z + ea * w4.z;  vz = vz > 0.f ? vz : 0.2f * vz;
        float vw = f23.y + b.w + ea * w4.w;  vw = vw > 0.f ? vw : 0.2f * vw;
        float lg = vx * at.x + vy * at.y + vz * at.z + vw * at.w;
        lg += __shfl_xor_sync(m16, lg, 8);
        lg += __shfl_xor_sync(m16, lg, 4);
        lg += __shfl_xor_sync(m16, lg, 2);
        lg += __shfl_xor_sync(m16, lg, 1);
        float p = __expf(lg);
        den += p;
        acc.x += p * f01.x; acc.y += p * f01.y; acc.z += p * f23.x; acc.w += p * f23.y;
    }
    __syncwarp();
    acc.x += __shfl_xor_sync(0xffffffffu, acc.x, 16);
    acc.y += __shfl_xor_sync(0xffffffffu, acc.y, 16);
    acc.z += __shfl_xor_sync(0xffffffffu, acc.z, 16);
    acc.w += __shfl_xor_sync(0xffffffffu, acc.w, 16);
    den   += __shfl_xor_sync(0xffffffffu, den, 16);
    easum += __shfl_xor_sync(0xffffffffu, easum, 16);

    // self-loop edge: src = dst, ea = mean of incoming edge attrs
    {
        float lea = easum / fmaxf((float)cnt, 1.f);
        uint2 u = *(const uint2*)&g_xlh[(size_t)d * 64 + cg * 4];
        float2 f01 = __half22float2(*(__half2*)&u.x);
        float2 f23 = __half22float2(*(__half2*)&u.y);
        float vx = f01.x + b.x + lea * w4.x;  vx = vx > 0.f ? vx : 0.2f * vx;
        float vy = f01.y + b.y + lea * w4.y;  vy = vy > 0.f ? vy : 0.2f * vy;
        float vz = f23.x + b.z + lea * w4.z;  vz = vz > 0.f ? vz : 0.2f * vz;
        float vw = f23.y + b.w + lea * w4.w;  vw = vw > 0.f ? vw : 0.2f * vw;
        float lg = vx * at.x + vy * at.y + vz * at.z + vw * at.w;
        lg += __shfl_xor_sync(0xffffffffu, lg, 8);
        lg += __shfl_xor_sync(0xffffffffu, lg, 4);
        lg += __shfl_xor_sync(0xffffffffu, lg, 2);
        lg += __shfl_xor_sync(0xffffffffu, lg, 1);
        float p = __expf(lg);
        den += p;
        acc.x += p * f01.x; acc.y += p * f01.y; acc.z += p * f23.x; acc.w += p * f23.y;
    }

    float inv = 1.f / (den + 1e-16f);
    float4 bias4 = __ldg((const float4*)&bias[cg * 4]);
    float h0 = acc.x * inv + bias4.x;  h0 = h0 > 0.f ? h0 : expm1f(h0);
    float h1 = acc.y * inv + bias4.y;  h1 = h1 > 0.f ? h1 : expm1f(h1);
    float h2 = acc.z * inv + bias4.z;  h2 = h2 > 0.f ? h2 : expm1f(h2);
    float h3 = acc.w * inv + bias4.w;  h3 = h3 > 0.f ? h3 : expm1f(h3);

    if (half == 0) {
        if (LAYER == 0) {
            *(float4*)&g_h1[(size_t)d * 64 + cg * 4] = make_float4(h0, h1, h2, h3);
        } else {
            int g = batch[d];
            float* ptr = &g_gsum[g * 64 + cg * 4];
            asm volatile("red.global.add.v4.f32 [%0], {%1, %2, %3, %4};"
                         :: "l"(ptr), "f"(h0), "f"(h1), "f"(h2), "f"(h3)
                         : "memory");
            if (cg == 0) atomicAdd(&g_gcnt[g], 1.f);
        }
    }
}

// ---------------- head: relu(fc1) -> BN(eval) -> fc3 ----------------
__global__ void k_head(const float* __restrict__ Wfc1, const float* __restrict__ bfc1,
                       const float* __restrict__ gamma, const float* __restrict__ beta,
                       const float* __restrict__ mean, const float* __restrict__ var,
                       const float* __restrict__ Wfc3, const float* __restrict__ bfc3,
                       float* __restrict__ out) {
    int g = threadIdx.x;
    if (g >= GG) return;
    float cnt = fmaxf(g_gcnt[g], 1.f);
    float pooled[64];
#pragma unroll
    for (int c = 0; c < 64; c++) pooled[c] = g_gsum[g * 64 + c] / cnt;
    float acc = bfc3[0];
    for (int j = 0; j < 32; j++) {
        float z = bfc1[j];
#pragma unroll
        for (int c = 0; c < 64; c++) z = fmaf(pooled[c], Wfc1[c * 32 + j], z);
        z = fmaxf(z, 0.f);
        z = (z - mean[j]) * rsqrtf(var[j] + 1e-5f) * gamma[j] + beta[j];
        acc = fmaf(z, Wfc3[j], acc);
    }
    out[g] = acc;
}

// ---------------- launch ----------------
extern "C" void kernel_launch(void* const* d_in, const int* in_sizes, int n_in,
                              void* d_out, int out_size) {
    const float* x      = (const float*)d_in[0];
    const int*   eidx   = (const int*)d_in[1];
    const float* eattr  = (const float*)d_in[2];
    const int*   batch  = (const int*)d_in[3];
    const float* Wl1 = (const float*)d_in[4];   const float* bl1 = (const float*)d_in[5];
    const float* Wr1 = (const float*)d_in[6];   const float* br1 = (const float*)d_in[7];
    const float* We1 = (const float*)d_in[8];   const float* att1 = (const float*)d_in[9];
    const float* bias1 = (const float*)d_in[10];
    const float* Wl2 = (const float*)d_in[11];  const float* bl2 = (const float*)d_in[12];
    const float* Wr2 = (const float*)d_in[13];  const float* br2 = (const float*)d_in[14];
    const float* We2 = (const float*)d_in[15];  const float* att2 = (const float*)d_in[16];
    const float* bias2 = (const float*)d_in[17];
    const float* Wfc1 = (const float*)d_in[18]; const float* bfc1 = (const float*)d_in[19];
    const float* gamma = (const float*)d_in[20]; const float* beta = (const float*)d_in[21];
    const float* mean = (const float*)d_in[22];  const float* var = (const float*)d_in[23];
    const float* Wfc3 = (const float*)d_in[24];  const float* bfc3 = (const float*)d_in[25];
    float* out = (float*)d_out;

    const int* e_src = eidx;        // edge_index[0]
    const int* e_dst = eidx + EE;   // edge_index[1]

    const int TB = 256;
    const int nBlocksN    = (NN + TB - 1) / TB;
    const int nBlocksE    = (EE + TB - 1) / TB;
    const int nBlocksGemm = (NN + 63) / 64;
    const int nBlocksWarp = (NN * 32 + TB - 1) / TB;    // warp per dst

    const int smem1 = (2 * 128 * 64 + 64 * 128) * 4;    // 96 KB
    const int smem2 = (2 * 64 * 64 + 64 * 64) * 4;      // 48 KB
    cudaFuncSetAttribute(k_gemm2<128, 0>, cudaFuncAttributeMaxDynamicSharedMemorySize, smem1);
    cudaFuncSetAttribute(k_gemm2<64, 1>,  cudaFuncAttributeMaxDynamicSharedMemorySize, smem2);

    // ---- CSR build (once; reused by both layers) ----
    k_init0<<<nBlocksN, TB>>>();
    k_hist<<<nBlocksE, TB>>>(e_dst);
    k_scan1<<<NB, 512>>>();
    k_scan3<<<NB, 512>>>();
    k_escatter<<<nBlocksE, TB>>>(e_src, e_dst, eattr);

    // ---- layer 1 ----
    k_gemm2<128, 0><<<nBlocksGemm, TB, smem1>>>(x, Wl1, bl1, Wr1, br1);
    k_edge_sorted<0><<<nBlocksWarp, TB>>>(We1, att1, bias1, nullptr);   // -> g_h1

    // ---- layer 2 ----
    k_gemm2<64, 1><<<nBlocksGemm, TB, smem2>>>(nullptr, Wl2, bl2, Wr2, br2);
    k_edge_sorted<1><<<nBlocksWarp, TB>>>(We2, att2, bias2, batch);     // -> pool

    // ---- head ----
    k_head<<<1, 64>>>(Wfc1, bfc1, gamma, beta, mean, var, Wfc3, bfc3, out);
}

// round 14
// speedup vs baseline: 1.1482x; 1.0502x over previous
#include <cuda_runtime.h>
#include <cuda_fp16.h>
#include <math.h>

#define NN 50000
#define EE 1600000
#define GG 64
#define NB 98            // (NN+511)/512 scan blocks

typedef unsigned long long u64;

// ---------------- device scratch ----------------
__device__ __align__(16) __half g_xlh[NN * 64];   // fp16 gather table
__device__ __align__(16) float g_xr[NN * 64];
__device__ __align__(16) float g_h1[NN * 64];
__device__ __align__(16) float g_gsum[GG * 64];
__device__ float g_gcnt[GG];
__device__ int   g_cnt[NN];
__device__ int   g_off[NN];
__device__ int   g_cursor[NN];
__device__ int   g_bsum[128];
__device__ __align__(16) int2 g_edges[EE];        // (src, ea-bits) interleaved

// ---------------- f32x2 helpers (FFMA2, PTX-only) ----------------
__device__ __forceinline__ u64 ffma2(u64 a, u64 b, u64 c) {
    u64 d;
    asm("fma.rn.f32x2 %0, %1, %2, %3;" : "=l"(d) : "l"(a), "l"(b), "l"(c));
    return d;
}
__device__ __forceinline__ u64 pack2(float x) {
    u64 d;
    asm("mov.b64 %0, {%1, %1};" : "=l"(d) : "f"(x));
    return d;
}
__device__ __forceinline__ void unpack2(u64 v, float& lo, float& hi) {
    asm("mov.b64 {%0, %1}, %2;" : "=f"(lo), "=f"(hi) : "l"(v));
}

// ---------------- init ----------------
__global__ void k_init0() {
    int i = blockIdx.x * blockDim.x + threadIdx.x;
    if (i < NN) g_cnt[i] = 0;
    if (i < GG * 64) g_gsum[i] = 0.f;
    if (i < GG) g_gcnt[i] = 0.f;
}

// ---------------- CSR build ----------------
__global__ void k_hist(const int* __restrict__ dst) {
    int e = blockIdx.x * blockDim.x + threadIdx.x;
    if (e >= EE) return;
    atomicAdd(&g_cnt[dst[e]], 1);
}

__global__ void k_scan1() {            // 512 threads/block, NB blocks
    __shared__ int wsum[16];
    int i = blockIdx.x * 512 + threadIdx.x;
    int lane = threadIdx.x & 31, wid = threadIdx.x >> 5;
    int v = (i < NN) ? g_cnt[i] : 0;
    int x = v;
#pragma unroll
    for (int o = 1; o < 32; o <<= 1) {
        int y = __shfl_up_sync(0xffffffffu, x, o);
        if (lane >= o) x += y;
    }
    if (lane == 31) wsum[wid] = x;
    __syncthreads();
    if (wid == 0) {
        int s = (lane < 16) ? wsum[lane] : 0;
#pragma unroll
        for (int o = 1; o < 16; o <<= 1) {
            int y = __shfl_up_sync(0xffffffffu, s, o);
            if (lane >= o) s += y;
        }
        if (lane < 16) wsum[lane] = s;
    }
    __syncthreads();
    int prefix = (wid > 0) ? wsum[wid - 1] : 0;
    if (i < NN) g_off[i] = prefix + x - v;        // exclusive within block
    if (threadIdx.x == 511) g_bsum[blockIdx.x] = prefix + x;  // block total
}

__global__ void k_scan3() {            // per-block prefix over block sums, then finalize
    __shared__ int bpref;
    int b = blockIdx.x;
    if (threadIdx.x < 32) {
        int s = 0;
        for (int j = threadIdx.x; j < b; j += 32) s += g_bsum[j];
#pragma unroll
        for (int o = 16; o; o >>= 1) s += __shfl_xor_sync(0xffffffffu, s, o);
        if (threadIdx.x == 0) bpref = s;
    }
    __syncthreads();
    int i = b * 512 + threadIdx.x;
    if (i < NN) {
        int o = g_off[i] + bpref;
        g_off[i] = o;
        g_cursor[i] = o;
    }
}

__global__ void k_escatter(const int* __restrict__ src, const int* __restrict__ dst,
                           const float* __restrict__ ea) {
    int e = blockIdx.x * blockDim.x + threadIdx.x;
    if (e >= EE) return;
    int d = dst[e];
    int pos = atomicAdd(&g_cursor[d], 1);
    g_edges[pos] = make_int2(src[e], __float_as_int(ea[e]));
}

// ---------------- fused dual GEMM: xl = X@Wl+bl (fp16 out), xr = X@Wr+br --------------
template <int K, int USE_H1>
__global__ __launch_bounds__(256) void k_gemm2(
        const float* __restrict__ Xg,
        const float* __restrict__ Wl, const float* __restrict__ bl,
        const float* __restrict__ Wr, const float* __restrict__ br) {
    extern __shared__ float sh[];
    float* Wls = sh;                 // K*64
    float* Wrs = sh + K * 64;        // K*64
    float* Xs  = sh + 2 * K * 64;    // 64*K

    int t = threadIdx.x;
    int base = blockIdx.x * 64;
    const float* __restrict__ X = USE_H1 ? g_h1 : Xg;

    for (int i = t; i < K * 16; i += 256) {
        *(float4*)&Wls[i * 4] = __ldg((const float4*)&Wl[i * 4]);
        *(float4*)&Wrs[i * 4] = __ldg((const float4*)&Wr[i * 4]);
    }
    const int K4 = K / 4;
    for (int i = t; i < 64 * K4; i += 256) {
        int row = i / K4, c4 = i - row * K4;
        int node = base + row;
        float4 v = make_float4(0.f, 0.f, 0.f, 0.f);
        if (node < NN) v = __ldg((const float4*)&X[(size_t)node * K + c4 * 4]);
        *(float4*)&Xs[row * K + c4 * 4] = v;
    }
    __syncthreads();

    int cg = t & 15;            // 4 output channels
    int ng = t >> 4;            // 4 nodes
    int nb = base + ng * 4;

    u64 bl0 = *(const u64*)&bl[cg * 4];
    u64 bl1 = *(const u64*)&bl[cg * 4 + 2];
    u64 br0 = *(const u64*)&br[cg * 4];
    u64 br1 = *(const u64*)&br[cg * 4 + 2];

    u64 accL[4][2], accR[4][2];
#pragma unroll
    for (int n = 0; n < 4; n++) {
        accL[n][0] = bl0; accL[n][1] = bl1;
        accR[n][0] = br0; accR[n][1] = br1;
    }

    const float* xs0 = &Xs[(ng * 4 + 0) * K];
    const float* xs1 = &Xs[(ng * 4 + 1) * K];
    const float* xs2 = &Xs[(ng * 4 + 2) * K];
    const float* xs3 = &Xs[(ng * 4 + 3) * K];

#pragma unroll 4
    for (int k = 0; k < K; k++) {
        ulonglong2 wl = *(const ulonglong2*)&Wls[k * 64 + cg * 4];
        ulonglong2 wr = *(const ulonglong2*)&Wrs[k * 64 + cg * 4];
        u64 x0 = pack2(xs0[k]);
        u64 x1 = pack2(xs1[k]);
        u64 x2 = pack2(xs2[k]);
        u64 x3 = pack2(xs3[k]);
        accL[0][0] = ffma2(x0, wl.x, accL[0][0]);  accL[0][1] = ffma2(x0, wl.y, accL[0][1]);
        accR[0][0] = ffma2(x0, wr.x, accR[0][0]);  accR[0][1] = ffma2(x0, wr.y, accR[0][1]);
        accL[1][0] = ffma2(x1, wl.x, accL[1][0]);  accL[1][1] = ffma2(x1, wl.y, accL[1][1]);
        accR[1][0] = ffma2(x1, wr.x, accR[1][0]);  accR[1][1] = ffma2(x1, wr.y, accR[1][1]);
        accL[2][0] = ffma2(x2, wl.x, accL[2][0]);  accL[2][1] = ffma2(x2, wl.y, accL[2][1]);
        accR[2][0] = ffma2(x2, wr.x, accR[2][0]);  accR[2][1] = ffma2(x2, wr.y, accR[2][1]);
        accL[3][0] = ffma2(x3, wl.x, accL[3][0]);  accL[3][1] = ffma2(x3, wl.y, accL[3][1]);
        accR[3][0] = ffma2(x3, wr.x, accR[3][0]);  accR[3][1] = ffma2(x3, wr.y, accR[3][1]);
    }

#pragma unroll
    for (int n = 0; n < 4; n++) {
        if (nb + n < NN) {
            float4 L, R;
            unpack2(accL[n][0], L.x, L.y);  unpack2(accL[n][1], L.z, L.w);
            unpack2(accR[n][0], R.x, R.y);  unpack2(accR[n][1], R.z, R.w);
            __half2 h01 = __floats2half2_rn(L.x, L.y);
            __half2 h23 = __floats2half2_rn(L.z, L.w);
            uint2 hv;
            hv.x = *(unsigned*)&h01;
            hv.y = *(unsigned*)&h23;
            *(uint2*)&g_xlh[(size_t)(nb + n) * 64 + cg * 4] = hv;
            *(float4*)&g_xr[(size_t)(nb + n) * 64 + cg * 4] = R;
        }
    }
}

// ---------------- warp-per-dst edge pass over CSR (fp16 xl gathers) — R6 exact ---------
template <int LAYER>
__global__ __launch_bounds__(256) void k_edge_sorted(
        const float* __restrict__ We, const float* __restrict__ att,
        const float* __restrict__ bias, const int* __restrict__ batch) {
    int gw = (blockIdx.x * 256 + threadIdx.x) >> 5;
    if (gw >= NN) return;
    int lane = threadIdx.x & 31;
    int half = lane >> 4, cg = lane & 15;
    unsigned m16 = 0xFFFFu << (half * 16);

    int d = gw;
    int off = g_off[d], cnt = g_cnt[d];
    int end = off + cnt;

    float4 b  = *(const float4*)&g_xr[(size_t)d * 64 + cg * 4];
    float4 w4 = __ldg((const float4*)&We[cg * 4]);
    float4 at = __ldg((const float4*)&att[cg * 4]);

    float4 acc = make_float4(0.f, 0.f, 0.f, 0.f);
    float den = 0.f, easum = 0.f;

    for (int i = off + half; i < end; i += 2) {
        int2 ed = g_edges[i];
        int s = ed.x;
        float ea = __int_as_float(ed.y);
        easum += ea;
        uint2 u = *(const uint2*)&g_xlh[(size_t)s * 64 + cg * 4];
        float2 f01 = __half22float2(*(__half2*)&u.x);
        float2 f23 = __half22float2(*(__half2*)&u.y);
        float vx = f01.x + b.x + ea * w4.x;  vx = vx > 0.f ? vx : 0.2f * vx;
        float vy = f01.y + b.y + ea * w4.y;  vy = vy > 0.f ? vy : 0.2f * vy;
        float vz = f23.x + b.z + ea * w4.z;  vz = vz > 0.f ? vz : 0.2f * vz;
        float vw = f23.y + b.w + ea * w4.w;  vw = vw > 0.f ? vw : 0.2f * vw;
        float lg = vx * at.x + vy * at.y + vz * at.z + vw * at.w;
        lg += __shfl_xor_sync(m16, lg, 8);
        lg += __shfl_xor_sync(m16, lg, 4);
        lg += __shfl_xor_sync(m16, lg, 2);
        lg += __shfl_xor_sync(m16, lg, 1);
        float p = __expf(lg);
        den += p;
        acc.x += p * f01.x; acc.y += p * f01.y; acc.z += p * f23.x; acc.w += p * f23.y;
    }
    __syncwarp();
    acc.x += __shfl_xor_sync(0xffffffffu, acc.x, 16);
    acc.y += __shfl_xor_sync(0xffffffffu, acc.y, 16);
    acc.z += __shfl_xor_sync(0xffffffffu, acc.z, 16);
    acc.w += __shfl_xor_sync(0xffffffffu, acc.w, 16);
    den   += __shfl_xor_sync(0xffffffffu, den, 16);
    easum += __shfl_xor_sync(0xffffffffu, easum, 16);

    // self-loop edge: src = dst, ea = mean of incoming edge attrs
    {
        float lea = easum / fmaxf((float)cnt, 1.f);
        uint2 u = *(const uint2*)&g_xlh[(size_t)d * 64 + cg * 4];
        float2 f01 = __half22float2(*(__half2*)&u.x);
        float2 f23 = __half22float2(*(__half2*)&u.y);
        float vx = f01.x + b.x + lea * w4.x;  vx = vx > 0.f ? vx : 0.2f * vx;
        float vy = f01.y + b.y + lea * w4.y;  vy = vy > 0.f ? vy : 0.2f * vy;
        float vz = f23.x + b.z + lea * w4.z;  vz = vz > 0.f ? vz : 0.2f * vz;
        float vw = f23.y + b.w + lea * w4.w;  vw = vw > 0.f ? vw : 0.2f * vw;
        float lg = vx * at.x + vy * at.y + vz * at.z + vw * at.w;
        lg += __shfl_xor_sync(0xffffffffu, lg, 8);
        lg += __shfl_xor_sync(0xffffffffu, lg, 4);
        lg += __shfl_xor_sync(0xffffffffu, lg, 2);
        lg += __shfl_xor_sync(0xffffffffu, lg, 1);
        float p = __expf(lg);
        den += p;
        acc.x += p * f01.x; acc.y += p * f01.y; acc.z += p * f23.x; acc.w += p * f23.y;
    }

    float inv = 1.f / (den + 1e-16f);
    float4 bias4 = __ldg((const float4*)&bias[cg * 4]);
    float h0 = acc.x * inv + bias4.x;  h0 = h0 > 0.f ? h0 : expm1f(h0);
    float h1 = acc.y * inv + bias4.y;  h1 = h1 > 0.f ? h1 : expm1f(h1);
    float h2 = acc.z * inv + bias4.z;  h2 = h2 > 0.f ? h2 : expm1f(h2);
    float h3 = acc.w * inv + bias4.w;  h3 = h3 > 0.f ? h3 : expm1f(h3);

    if (half == 0) {
        if (LAYER == 0) {
            *(float4*)&g_h1[(size_t)d * 64 + cg * 4] = make_float4(h0, h1, h2, h3);
        } else {
            int g = batch[d];
            float* ptr = &g_gsum[g * 64 + cg * 4];
            asm volatile("red.global.add.v4.f32 [%0], {%1, %2, %3, %4};"
                         :: "l"(ptr), "f"(h0), "f"(h1), "f"(h2), "f"(h3)
                         : "memory");
            if (cg == 0) atomicAdd(&g_gcnt[g], 1.f);
        }
    }
}

// ---------------- head: relu(fc1) -> BN(eval) -> fc3 ----------------
__global__ void k_head(const float* __restrict__ Wfc1, const float* __restrict__ bfc1,
                       const float* __restrict__ gamma, const float* __restrict__ beta,
                       const float* __restrict__ mean, const float* __restrict__ var,
                       const float* __restrict__ Wfc3, const float* __restrict__ bfc3,
                       float* __restrict__ out) {
    int g = threadIdx.x;
    if (g >= GG) return;
    float cnt = fmaxf(g_gcnt[g], 1.f);
    float pooled[64];
#pragma unroll
    for (int c = 0; c < 64; c++) pooled[c] = g_gsum[g * 64 + c] / cnt;
    float acc = bfc3[0];
    for (int j = 0; j < 32; j++) {
        float z = bfc1[j];
#pragma unroll
        for (int c = 0; c < 64; c++) z = fmaf(pooled[c], Wfc1[c * 32 + j], z);
        z = fmaxf(z, 0.f);
        z = (z - mean[j]) * rsqrtf(var[j] + 1e-5f) * gamma[j] + beta[j];
        acc = fmaf(z, Wfc3[j], acc);
    }
    out[g] = acc;
}

// ---------------- launch (stream-forked graph: CSR build || gemm1) ----------------
extern "C" void kernel_launch(void* const* d_in, const int* in_sizes, int n_in,
                              void* d_out, int out_size) {
    const float* x      = (const float*)d_in[0];
    const int*   eidx   = (const int*)d_in[1];
    const float* eattr  = (const float*)d_in[2];
    const int*   batch  = (const int*)d_in[3];
    const float* Wl1 = (const float*)d_in[4];   const float* bl1 = (const float*)d_in[5];
    const float* Wr1 = (const float*)d_in[6];   const float* br1 = (const float*)d_in[7];
    const float* We1 = (const float*)d_in[8];   const float* att1 = (const float*)d_in[9];
    const float* bias1 = (const float*)d_in[10];
    const float* Wl2 = (const float*)d_in[11];  const float* bl2 = (const float*)d_in[12];
    const float* Wr2 = (const float*)d_in[13];  const float* br2 = (const float*)d_in[14];
    const float* We2 = (const float*)d_in[15];  const float* att2 = (const float*)d_in[16];
    const float* bias2 = (const float*)d_in[17];
    const float* Wfc1 = (const float*)d_in[18]; const float* bfc1 = (const float*)d_in[19];
    const float* gamma = (const float*)d_in[20]; const float* beta = (const float*)d_in[21];
    const float* mean = (const float*)d_in[22];  const float* var = (const float*)d_in[23];
    const float* Wfc3 = (const float*)d_in[24];  const float* bfc3 = (const float*)d_in[25];
    float* out = (float*)d_out;

    const int* e_src = eidx;        // edge_index[0]
    const int* e_dst = eidx + EE;   // edge_index[1]

    const int TB = 256;
    const int nBlocksN    = (NN + TB - 1) / TB;
    const int nBlocksE    = (EE + TB - 1) / TB;
    const int nBlocksGemm = (NN + 63) / 64;
    const int nBlocksWarp = (NN * 32 + TB - 1) / TB;    // warp per dst

    const int smem1 = (2 * 128 * 64 + 64 * 128) * 4;    // 96 KB
    const int smem2 = (2 * 64 * 64 + 64 * 64) * 4;      // 48 KB

    // one-time host-side setup (no device allocs)
    static cudaStream_t sB = nullptr;
    static cudaEvent_t evFork = nullptr, evJoin = nullptr;
    if (sB == nullptr) {
        cudaStreamCreateWithFlags(&sB, cudaStreamNonBlocking);
        cudaEventCreateWithFlags(&evFork, cudaEventDisableTiming);
        cudaEventCreateWithFlags(&evJoin, cudaEventDisableTiming);
        cudaFuncSetAttribute(k_gemm2<128, 0>, cudaFuncAttributeMaxDynamicSharedMemorySize, smem1);
        cudaFuncSetAttribute(k_gemm2<64, 1>,  cudaFuncAttributeMaxDynamicSharedMemorySize, smem2);
    }

    // ---- fork: CSR build on stream 0, layer-1 GEMM on stream sB (independent) ----
    cudaEventRecord(evFork, 0);
    cudaStreamWaitEvent(sB, evFork, 0);

    // stream 0: CSR build chain
    k_init0<<<nBlocksN, TB>>>();
    k_hist<<<nBlocksE, TB>>>(e_dst);
    k_scan1<<<NB, 512>>>();
    k_scan3<<<NB, 512>>>();
    k_escatter<<<nBlocksE, TB>>>(e_src, e_dst, eattr);

    // stream sB: gemm1 (reads only x + weights; writes g_xlh/g_xr)
    k_gemm2<128, 0><<<nBlocksGemm, TB, smem1, sB>>>(x, Wl1, bl1, Wr1, br1);

    // join
    cudaEventRecord(evJoin, sB);
    cudaStreamWaitEvent(0, evJoin, 0);

    // ---- layer 1 edge pass ----
    k_edge_sorted<0><<<nBlocksWarp, TB>>>(We1, att1, bias1, nullptr);   // -> g_h1

    // ---- layer 2 ----
    k_gemm2<64, 1><<<nBlocksGemm, TB, smem2>>>(nullptr, Wl2, bl2, Wr2, br2);
    k_edge_sorted<1><<<nBlocksWarp, TB>>>(We2, att2, bias2, batch);     // -> pool

    // ---- head ----
    k_head<<<1, 64>>>(Wfc1, bfc1, gamma, beta, mean, var, Wfc3, bfc3, out);
}